// round 4
// baseline (speedup 1.0000x reference)
#include <cuda_runtime.h>

#define NROWS 8192
#define DDIM  256
#define BI 64
#define BJ 64
#define BK 16

// Scratch (no allocations allowed)
__device__ float  g_n1sq[NROWS];
__device__ float  g_n2sq[NROWS];
__device__ float  g_npsq[NROWS];
__device__ double g_acc;

// ---------------------------------------------------------------------------
// Reset accumulator each launch (graph replays must be deterministic)
// ---------------------------------------------------------------------------
__global__ void mqjs_init_kernel() {
    g_acc = 0.0;
}

// ---------------------------------------------------------------------------
// Precompute ||x1_r||^2, ||x2_r||^2, ||(x1_r+x2_r)/2||^2 per row.
// One warp per row; each lane handles 2 float4's (256 floats / 32 lanes).
// ---------------------------------------------------------------------------
__global__ void mqjs_norms_kernel(const float* __restrict__ x1,
                                  const float* __restrict__ x2) {
    int warp = threadIdx.x >> 5;
    int lane = threadIdx.x & 31;
    int row  = blockIdx.x * 8 + warp;

    const float4* p1 = reinterpret_cast<const float4*>(x1 + (size_t)row * DDIM);
    const float4* p2 = reinterpret_cast<const float4*>(x2 + (size_t)row * DDIM);

    float s1 = 0.f, s2 = 0.f, sp = 0.f;
#pragma unroll
    for (int it = 0; it < 2; it++) {
        float4 a = p1[lane + it * 32];
        float4 b = p2[lane + it * 32];
        s1 += a.x * a.x + a.y * a.y + a.z * a.z + a.w * a.w;
        s2 += b.x * b.x + b.y * b.y + b.z * b.z + b.w * b.w;
        float px = 0.5f * (a.x + b.x);
        float py = 0.5f * (a.y + b.y);
        float pz = 0.5f * (a.z + b.z);
        float pw = 0.5f * (a.w + b.w);
        sp += px * px + py * py + pz * pz + pw * pw;
    }
#pragma unroll
    for (int off = 16; off > 0; off >>= 1) {
        s1 += __shfl_xor_sync(0xFFFFFFFFu, s1, off);
        s2 += __shfl_xor_sync(0xFFFFFFFFu, s2, off);
        sp += __shfl_xor_sync(0xFFFFFFFFu, sp, off);
    }
    if (lane == 0) {
        g_n1sq[row] = s1;
        g_n2sq[row] = s2;
        g_npsq[row] = sp;
    }
}

// ---------------------------------------------------------------------------
// Fused triple-Gram + log epilogue.
// Block tile: 64(i) x 64(j). 256 threads, 4x4 micro-tile per thread.
// Per (i,j): s11 = x1_i . p_j ; s22 = x2_i . p_j ; saa = x1_i . x1_j
// Contribution: 0.5 log(max(d1,1)) + 0.5 log(max(d2,1)) - c * 0.5 log(max(ds,1))
// ---------------------------------------------------------------------------
__global__ __launch_bounds__(256, 2)
void mqjs_main_kernel(const float* __restrict__ x1,
                      const float* __restrict__ x2) {
    // k-major smem tiles: inner-loop reads are conflict-free LDS.128
    __shared__ float sA1[BK][BI];   // x1 i-rows  (A side)
    __shared__ float sA2[BK][BI];   // x2 i-rows  (A side)
    __shared__ float sBp[BK][BJ];   // p  j-rows  (B side)
    __shared__ float sB1[BK][BJ];   // x1 j-rows  (B side)
    __shared__ float sRed[256];

    const int ib = blockIdx.y * BI;
    const int jb = blockIdx.x * BJ;
    const int tid = threadIdx.x;
    const int tx = tid & 15;        // j-quad index (0..15)
    const int ty = tid >> 4;        // i-quad index (0..15)

    // G2S loading map: each thread loads one float4 per tile per chunk
    const int lr = tid >> 2;          // row within tile (0..63)
    const int lc = (tid & 3) << 2;    // k offset within chunk (0,4,8,12)

    float s11[4][4], s22[4][4], saa[4][4];
#pragma unroll
    for (int a = 0; a < 4; a++)
#pragma unroll
        for (int b = 0; b < 4; b++) { s11[a][b] = 0.f; s22[a][b] = 0.f; saa[a][b] = 0.f; }

    for (int k0 = 0; k0 < DDIM; k0 += BK) {
        float4 a1 = *reinterpret_cast<const float4*>(x1 + (size_t)(ib + lr) * DDIM + k0 + lc);
        float4 a2 = *reinterpret_cast<const float4*>(x2 + (size_t)(ib + lr) * DDIM + k0 + lc);
        float4 b1 = *reinterpret_cast<const float4*>(x1 + (size_t)(jb + lr) * DDIM + k0 + lc);
        float4 b2 = *reinterpret_cast<const float4*>(x2 + (size_t)(jb + lr) * DDIM + k0 + lc);

        __syncthreads();  // previous iteration's reads done before overwrite
        // transpose-store into k-major tiles; form p on the fly
        sA1[lc + 0][lr] = a1.x; sA1[lc + 1][lr] = a1.y; sA1[lc + 2][lr] = a1.z; sA1[lc + 3][lr] = a1.w;
        sA2[lc + 0][lr] = a2.x; sA2[lc + 1][lr] = a2.y; sA2[lc + 2][lr] = a2.z; sA2[lc + 3][lr] = a2.w;
        sB1[lc + 0][lr] = b1.x; sB1[lc + 1][lr] = b1.y; sB1[lc + 2][lr] = b1.z; sB1[lc + 3][lr] = b1.w;
        sBp[lc + 0][lr] = 0.5f * (b1.x + b2.x);
        sBp[lc + 1][lr] = 0.5f * (b1.y + b2.y);
        sBp[lc + 2][lr] = 0.5f * (b1.z + b2.z);
        sBp[lc + 3][lr] = 0.5f * (b1.w + b2.w);
        __syncthreads();

#pragma unroll
        for (int k = 0; k < BK; k++) {
            float4 ra1 = *reinterpret_cast<const float4*>(&sA1[k][ty << 2]);
            float4 ra2 = *reinterpret_cast<const float4*>(&sA2[k][ty << 2]);
            float4 rbp = *reinterpret_cast<const float4*>(&sBp[k][tx << 2]);
            float4 rb1 = *reinterpret_cast<const float4*>(&sB1[k][tx << 2]);

            float A1[4] = {ra1.x, ra1.y, ra1.z, ra1.w};
            float A2[4] = {ra2.x, ra2.y, ra2.z, ra2.w};
            float BP[4] = {rbp.x, rbp.y, rbp.z, rbp.w};
            float B1[4] = {rb1.x, rb1.y, rb1.z, rb1.w};
#pragma unroll
            for (int ii = 0; ii < 4; ii++) {
#pragma unroll
                for (int jj = 0; jj < 4; jj++) {
                    s11[ii][jj] = fmaf(A1[ii], BP[jj], s11[ii][jj]);
                    s22[ii][jj] = fmaf(A2[ii], BP[jj], s22[ii][jj]);
                    saa[ii][jj] = fmaf(A1[ii], B1[jj], saa[ii][jj]);
                }
            }
        }
    }

    // ---- epilogue: distances -> logs -> per-thread partial sum ----
    const float cse = (float)NROWS / (float)(NROWS - 1);
    float n1i[4], n2i[4], npj[4], n1j[4];
#pragma unroll
    for (int ii = 0; ii < 4; ii++) {
        int gi = ib + (ty << 2) + ii;
        n1i[ii] = g_n1sq[gi];
        n2i[ii] = g_n2sq[gi];
    }
#pragma unroll
    for (int jj = 0; jj < 4; jj++) {
        int gj = jb + (tx << 2) + jj;
        npj[jj] = g_npsq[gj];
        n1j[jj] = g_n1sq[gj];
    }

    float part = 0.f;
#pragma unroll
    for (int ii = 0; ii < 4; ii++) {
#pragma unroll
        for (int jj = 0; jj < 4; jj++) {
            float d1 = n1i[ii] + npj[jj] - 2.f * s11[ii][jj];
            float d2 = n2i[ii] + npj[jj] - 2.f * s22[ii][jj];
            float ds = n1i[ii] + n1j[jj] - 2.f * saa[ii][jj];
            part += 0.5f * __logf(fmaxf(d1, 1.f));
            part += 0.5f * __logf(fmaxf(d2, 1.f));
            part -= cse * 0.5f * __logf(fmaxf(ds, 1.f));
        }
    }

    // ---- block reduction ----
    sRed[tid] = part;
    __syncthreads();
#pragma unroll
    for (int s = 128; s > 0; s >>= 1) {
        if (tid < s) sRed[tid] += sRed[tid + s];
        __syncthreads();
    }
    if (tid == 0) atomicAdd(&g_acc, (double)sRed[0]);
}

// ---------------------------------------------------------------------------
__global__ void mqjs_finalize_kernel(float* out) {
    out[0] = (float)(g_acc / (double)NROWS);
}

// ---------------------------------------------------------------------------
extern "C" void kernel_launch(void* const* d_in, const int* in_sizes, int n_in,
                              void* d_out, int out_size) {
    const float* x1 = (const float*)d_in[0];   // input
    const float* x2 = (const float*)d_in[1];   // target
    float* out = (float*)d_out;

    mqjs_init_kernel<<<1, 1>>>();
    mqjs_norms_kernel<<<NROWS / 8, 256>>>(x1, x2);
    dim3 grid(NROWS / BJ, NROWS / BI);   // (128, 128)
    mqjs_main_kernel<<<grid, 256>>>(x1, x2);
    mqjs_finalize_kernel<<<1, 1>>>(out);
}

// round 6
// speedup vs baseline: 3.1229x; 3.1229x over previous
#include <cuda_runtime.h>
#include <cstdint>

#define NROWS 8192
#define DDIM  256
#define TM 128
#define TN 64
#define KC 32                         // floats per k-chunk (128 B rows)
#define NCHUNK (DDIM / KC)            // 8
#define OFF_A1 0
#define OFF_A2 16384
#define OFF_B1 32768
#define OFF_BP 40960
#define STAGE_BYTES 49152
#define DSMEM_BYTES (2 * STAGE_BYTES + 1024)

// Scratch (no allocations allowed)
__device__ float  g_n1sq[NROWS];
__device__ float  g_n2sq[NROWS];
__device__ float  g_npsq[NROWS];
__device__ double g_acc;

// ---------------------------------------------------------------------------
// Helpers (generic PTX only — no sm_103a-specific features; ptxas here
// targets plain sm_103 so tcgen05/TMEM are unavailable)
// ---------------------------------------------------------------------------
__device__ __forceinline__ uint32_t smem_u32(const void* p) {
    uint32_t a;
    asm("{ .reg .u64 t; cvta.to.shared.u64 t, %1; cvt.u32.u64 %0, t; }"
        : "=r"(a) : "l"(p));
    return a;
}

__device__ __forceinline__ uint32_t f2tf32(float x) {
    uint32_t r;
    asm("cvt.rna.tf32.f32 %0, %1;" : "=r"(r) : "f"(x));
    return r;
}

__device__ __forceinline__ void sts128(uint32_t addr, uint32_t a, uint32_t b,
                                       uint32_t c, uint32_t d) {
    asm volatile("st.shared.v4.b32 [%0], {%1,%2,%3,%4};"
                 :: "r"(addr), "r"(a), "r"(b), "r"(c), "r"(d) : "memory");
}

__device__ __forceinline__ void ldmx4(uint32_t* r, uint32_t addr) {
    asm volatile("ldmatrix.sync.aligned.m8n8.x4.shared.b16 {%0,%1,%2,%3}, [%4];"
                 : "=r"(r[0]), "=r"(r[1]), "=r"(r[2]), "=r"(r[3]) : "r"(addr));
}

__device__ __forceinline__ void mma_tf32(float* d, const uint32_t* a,
                                         const uint32_t* b) {
    asm volatile(
        "mma.sync.aligned.m16n8k8.row.col.f32.tf32.tf32.f32 "
        "{%0,%1,%2,%3}, {%4,%5,%6,%7}, {%8,%9}, {%0,%1,%2,%3};"
        : "+f"(d[0]), "+f"(d[1]), "+f"(d[2]), "+f"(d[3])
        : "r"(a[0]), "r"(a[1]), "r"(a[2]), "r"(a[3]), "r"(b[0]), "r"(b[1]));
}

// ---------------------------------------------------------------------------
__global__ void mqjs_init_kernel() { g_acc = 0.0; }

// Per-row norms: ||x1||^2, ||x2||^2, ||(x1+x2)/2||^2.  One warp per row.
__global__ void mqjs_norms_kernel(const float* __restrict__ x1,
                                  const float* __restrict__ x2) {
    int warp = threadIdx.x >> 5;
    int lane = threadIdx.x & 31;
    int row  = blockIdx.x * 8 + warp;

    const float4* p1 = reinterpret_cast<const float4*>(x1 + (size_t)row * DDIM);
    const float4* p2 = reinterpret_cast<const float4*>(x2 + (size_t)row * DDIM);

    float s1 = 0.f, s2 = 0.f, sp = 0.f;
#pragma unroll
    for (int it = 0; it < 2; it++) {
        float4 a = p1[lane + it * 32];
        float4 b = p2[lane + it * 32];
        s1 += a.x * a.x + a.y * a.y + a.z * a.z + a.w * a.w;
        s2 += b.x * b.x + b.y * b.y + b.z * b.z + b.w * b.w;
        float px = 0.5f * (a.x + b.x), py = 0.5f * (a.y + b.y);
        float pz = 0.5f * (a.z + b.z), pw = 0.5f * (a.w + b.w);
        sp += px * px + py * py + pz * pz + pw * pw;
    }
#pragma unroll
    for (int off = 16; off > 0; off >>= 1) {
        s1 += __shfl_xor_sync(0xFFFFFFFFu, s1, off);
        s2 += __shfl_xor_sync(0xFFFFFFFFu, s2, off);
        sp += __shfl_xor_sync(0xFFFFFFFFu, sp, off);
    }
    if (lane == 0) { g_n1sq[row] = s1; g_n2sq[row] = s2; g_npsq[row] = sp; }
}

// ---------------------------------------------------------------------------
// Fused triple-Gram via mma.sync tf32:
//   D1 = X1 . P^T, D2 = X2 . P^T, D3 = X1 . X1^T   (P = (X1+X2)/2)
// CTA tile 128(i) x 64(j), 8 warps, warp tile 32x32.
// Smem tiles: 128B rows, XOR-swizzled (chunk ^= row&7) for conflict-free
// STS.128 and ldmatrix.
// ---------------------------------------------------------------------------
__global__ __launch_bounds__(256, 1)
void mqjs_mma_kernel(const float* __restrict__ x1,
                     const float* __restrict__ x2) {
    extern __shared__ char dsm[];
    __shared__ float s_npj[TN];
    __shared__ float s_n1j[TN];
    __shared__ float s_red[8];

    const int tid  = threadIdx.x;
    const int lane = tid & 31;
    const int wid  = tid >> 5;
    const int wm   = wid & 3;          // warp m index 0..3
    const int wn   = wid >> 2;         // warp n index 0..1
    const int mb_w = wm * 32;
    const int nb_w = wn * 32;
    const int ib = blockIdx.y * TM;
    const int jb = blockIdx.x * TN;

    const uint32_t dsm_u  = smem_u32(dsm);
    const uint32_t base_u = (dsm_u + 1023u) & ~1023u;   // 1024-align tiles

    if (tid < TN) {
        s_npj[tid] = g_npsq[jb + tid];
        s_n1j[tid] = g_n1sq[jb + tid];
    }

    // ---- G2S per-thread constants ----
    const float4* x1v = reinterpret_cast<const float4*>(x1);
    const float4* x2v = reinterpret_cast<const float4*>(x2);
    int aR[4], aC[4]; uint32_t aSts[4];
#pragma unroll
    for (int rep = 0; rep < 4; rep++) {
        int idx = tid + rep * 256;             // 0..1023
        int r = idx >> 3, c = idx & 7;
        aR[rep] = r; aC[rep] = c;
        aSts[rep] = (uint32_t)(r * 128 + ((c ^ (r & 7)) << 4));
    }
    int bR[2], bC[2]; uint32_t bSts[2];
#pragma unroll
    for (int rep = 0; rep < 2; rep++) {
        int idx = tid + rep * 256;             // 0..511
        int r = idx >> 3, c = idx & 7;
        bR[rep] = r; bC[rep] = c;
        bSts[rep] = (uint32_t)(r * 128 + ((c ^ (r & 7)) << 4));
    }

    // ---- ldmatrix per-lane constants ----
    // A fragments (m16k8): reg0/1 from row groups, reg2/3 from k+4 chunk
    const int arow = (lane & 7) | (((lane >> 3) & 1) << 3);   // 0..15
    const uint32_t ahi16 = (uint32_t)(((lane >> 4) & 1) << 4);
    const uint32_t aswz  = (uint32_t)((arow & 7) << 4);
    const uint32_t aRow0 = (uint32_t)((mb_w + arow) * 128);   // mt=0
    // B fragments (k8n8 from [n][k] storage)
    const int brow = (lane & 7) | (((lane >> 4) & 1) << 3);
    const uint32_t bhi16 = (uint32_t)(((lane >> 3) & 1) << 4);
    const uint32_t bswz  = (uint32_t)((brow & 7) << 4);
    const uint32_t bRow0 = (uint32_t)((nb_w + brow) * 128);

    // ---- accumulators ----
    float acc1[2][4][4], acc2[2][4][4], acc3[2][4][4];
#pragma unroll
    for (int mt = 0; mt < 2; mt++)
#pragma unroll
        for (int n8 = 0; n8 < 4; n8++)
#pragma unroll
            for (int e = 0; e < 4; e++) {
                acc1[mt][n8][e] = 0.f; acc2[mt][n8][e] = 0.f; acc3[mt][n8][e] = 0.f;
            }

    float4 ra1[4], ra2[4], rb1[2], rb2[2];

#define LDG_CHUNK(kc)                                                          \
    {                                                                          \
        _Pragma("unroll")                                                      \
        for (int rep = 0; rep < 4; rep++) {                                    \
            size_t g = (size_t)(ib + aR[rep]) * (DDIM / 4) + (kc) * 8 + aC[rep]; \
            ra1[rep] = __ldg(&x1v[g]);                                         \
            ra2[rep] = __ldg(&x2v[g]);                                         \
        }                                                                      \
        _Pragma("unroll")                                                      \
        for (int rep = 0; rep < 2; rep++) {                                    \
            size_t g = (size_t)(jb + bR[rep]) * (DDIM / 4) + (kc) * 8 + bC[rep]; \
            rb1[rep] = __ldg(&x1v[g]);                                         \
            rb2[rep] = __ldg(&x2v[g]);                                         \
        }                                                                      \
    }

#define STS_CHUNK(stg)                                                         \
    {                                                                          \
        _Pragma("unroll")                                                      \
        for (int rep = 0; rep < 4; rep++) {                                    \
            sts128((stg) + OFF_A1 + aSts[rep], f2tf32(ra1[rep].x),             \
                   f2tf32(ra1[rep].y), f2tf32(ra1[rep].z), f2tf32(ra1[rep].w)); \
            sts128((stg) + OFF_A2 + aSts[rep], f2tf32(ra2[rep].x),             \
                   f2tf32(ra2[rep].y), f2tf32(ra2[rep].z), f2tf32(ra2[rep].w)); \
        }                                                                      \
        _Pragma("unroll")                                                      \
        for (int rep = 0; rep < 2; rep++) {                                    \
            sts128((stg) + OFF_B1 + bSts[rep], f2tf32(rb1[rep].x),             \
                   f2tf32(rb1[rep].y), f2tf32(rb1[rep].z), f2tf32(rb1[rep].w)); \
            sts128((stg) + OFF_BP + bSts[rep],                                 \
                   f2tf32(0.5f * (rb1[rep].x + rb2[rep].x)),                   \
                   f2tf32(0.5f * (rb1[rep].y + rb2[rep].y)),                   \
                   f2tf32(0.5f * (rb1[rep].z + rb2[rep].z)),                   \
                   f2tf32(0.5f * (rb1[rep].w + rb2[rep].w)));                  \
        }                                                                      \
    }

    // prologue: fill stage 0
    LDG_CHUNK(0);
    STS_CHUNK(base_u);
    __syncthreads();

    for (int c = 0; c < NCHUNK; c++) {
        const int b = c & 1;
        const uint32_t stg = base_u + (uint32_t)b * STAGE_BYTES;
        if (c < NCHUNK - 1) LDG_CHUNK(c + 1);

#pragma unroll
        for (int ks = 0; ks < 4; ks++) {
            const uint32_t ak = ((uint32_t)(ks * 32) + ahi16) ^ aswz;
            const uint32_t bk = ((uint32_t)(ks * 32) + bhi16) ^ bswz;
            uint32_t a1f[8], a2f[8], bpf[8], b1f[8];
            ldmx4(a1f + 0, stg + OFF_A1 + aRow0 + ak);
            ldmx4(a1f + 4, stg + OFF_A1 + aRow0 + 2048 + ak);
            ldmx4(a2f + 0, stg + OFF_A2 + aRow0 + ak);
            ldmx4(a2f + 4, stg + OFF_A2 + aRow0 + 2048 + ak);
            ldmx4(bpf + 0, stg + OFF_BP + bRow0 + bk);
            ldmx4(bpf + 4, stg + OFF_BP + bRow0 + 2048 + bk);
            ldmx4(b1f + 0, stg + OFF_B1 + bRow0 + bk);
            ldmx4(b1f + 4, stg + OFF_B1 + bRow0 + 2048 + bk);
#pragma unroll
            for (int mt = 0; mt < 2; mt++) {
#pragma unroll
                for (int n8 = 0; n8 < 4; n8++) {
                    mma_tf32(acc1[mt][n8], a1f + mt * 4, bpf + n8 * 2);
                    mma_tf32(acc2[mt][n8], a2f + mt * 4, bpf + n8 * 2);
                    mma_tf32(acc3[mt][n8], a1f + mt * 4, b1f + n8 * 2);
                }
            }
        }

        if (c < NCHUNK - 1) STS_CHUNK(base_u + (uint32_t)(1 - b) * STAGE_BYTES);
        __syncthreads();
    }

    // ---- epilogue: distances -> logs -> partial sum ----
    const float cse = (float)NROWS / (float)(NROWS - 1);
    const int r0base = ib + mb_w + (lane >> 2);
    const int c0base = nb_w + (lane & 3) * 2;   // local j within CTA tile

    float part = 0.f;
#pragma unroll
    for (int mt = 0; mt < 2; mt++) {
        const int ri0 = r0base + mt * 16;
        const int ri1 = ri0 + 8;
        const float n1a = g_n1sq[ri0], n1b = g_n1sq[ri1];
        const float n2a = g_n2sq[ri0], n2b = g_n2sq[ri1];
#pragma unroll
        for (int n8 = 0; n8 < 4; n8++) {
            const int jl = c0base + n8 * 8;
            const float np0 = s_npj[jl], np1 = s_npj[jl + 1];
            const float nj0 = s_n1j[jl], nj1 = s_n1j[jl + 1];
            const float* d1 = acc1[mt][n8];
            const float* d2 = acc2[mt][n8];
            const float* d3 = acc3[mt][n8];
            part += 0.5f * __logf(fmaxf(n1a + np0 - 2.f * d1[0], 1.f));
            part += 0.5f * __logf(fmaxf(n1a + np1 - 2.f * d1[1], 1.f));
            part += 0.5f * __logf(fmaxf(n1b + np0 - 2.f * d1[2], 1.f));
            part += 0.5f * __logf(fmaxf(n1b + np1 - 2.f * d1[3], 1.f));
            part += 0.5f * __logf(fmaxf(n2a + np0 - 2.f * d2[0], 1.f));
            part += 0.5f * __logf(fmaxf(n2a + np1 - 2.f * d2[1], 1.f));
            part += 0.5f * __logf(fmaxf(n2b + np0 - 2.f * d2[2], 1.f));
            part += 0.5f * __logf(fmaxf(n2b + np1 - 2.f * d2[3], 1.f));
            part -= cse * 0.5f * __logf(fmaxf(n1a + nj0 - 2.f * d3[0], 1.f));
            part -= cse * 0.5f * __logf(fmaxf(n1a + nj1 - 2.f * d3[1], 1.f));
            part -= cse * 0.5f * __logf(fmaxf(n1b + nj0 - 2.f * d3[2], 1.f));
            part -= cse * 0.5f * __logf(fmaxf(n1b + nj1 - 2.f * d3[3], 1.f));
        }
    }

    // ---- reduction ----
#pragma unroll
    for (int off = 16; off > 0; off >>= 1)
        part += __shfl_xor_sync(0xFFFFFFFFu, part, off);
    if (lane == 0) s_red[wid] = part;
    __syncthreads();
    if (tid == 0) {
        float tot = 0.f;
#pragma unroll
        for (int w = 0; w < 8; w++) tot += s_red[w];
        atomicAdd(&g_acc, (double)tot);
    }
}

// ---------------------------------------------------------------------------
__global__ void mqjs_finalize_kernel(float* out) {
    out[0] = (float)(g_acc / (double)NROWS);
}

// ---------------------------------------------------------------------------
extern "C" void kernel_launch(void* const* d_in, const int* in_sizes, int n_in,
                              void* d_out, int out_size) {
    const float* x1 = (const float*)d_in[0];   // input
    const float* x2 = (const float*)d_in[1];   // target
    float* out = (float*)d_out;

    cudaFuncSetAttribute(mqjs_mma_kernel,
                         cudaFuncAttributeMaxDynamicSharedMemorySize, DSMEM_BYTES);

    mqjs_init_kernel<<<1, 1>>>();
    mqjs_norms_kernel<<<NROWS / 8, 256>>>(x1, x2);
    dim3 grid(NROWS / TN, NROWS / TM);   // (128, 64)
    mqjs_mma_kernel<<<grid, 256, DSMEM_BYTES>>>(x1, x2);
    mqjs_finalize_kernel<<<1, 1>>>(out);
}

// round 10
// speedup vs baseline: 6.8255x; 2.1856x over previous
#include <cuda_runtime.h>
#include <cstdint>

#define NROWS 8192
#define DDIM  256
#define NT    128                     // 64-row tiles per dimension
#define TS    64                      // tile size
#define NTILES (NT * (NT + 1) / 2)    // 8256 upper-triangle tile pairs
#define KC 32                         // floats per k-chunk (128 B rows)
#define NCHUNK (DDIM / KC)            // 8
#define OFF_X1I 0
#define OFF_PI  8192
#define OFF_X1J 16384
#define OFF_PJ  24576
#define STAGE_BYTES 32768
#define DSMEM_BYTES (2 * STAGE_BYTES + 1024)

// Scratch (no allocations allowed)
__device__ float    g_n1sq[NROWS];
__device__ float    g_n2sq[NROWS];
__device__ float    g_npsq[NROWS];
__device__ uint32_t g_x1t[NROWS * DDIM];   // tf32-rounded x1 bits
__device__ uint32_t g_pt [NROWS * DDIM];   // tf32-rounded p  bits
__device__ double   g_acc;

// ---------------------------------------------------------------------------
// Helpers (generic sm_80+ PTX only — ptxas here targets plain sm_103)
// ---------------------------------------------------------------------------
__device__ __forceinline__ uint32_t smem_u32(const void* p) {
    uint32_t a;
    asm("{ .reg .u64 t; cvta.to.shared.u64 t, %1; cvt.u32.u64 %0, t; }"
        : "=r"(a) : "l"(p));
    return a;
}

__device__ __forceinline__ uint32_t f2tf32(float x) {
    uint32_t r;
    asm("cvt.rna.tf32.f32 %0, %1;" : "=r"(r) : "f"(x));
    return r;
}

__device__ __forceinline__ void cp_async16(uint32_t smem_addr, const void* gptr) {
    asm volatile("cp.async.cg.shared.global [%0], [%1], 16;"
                 :: "r"(smem_addr), "l"(gptr) : "memory");
}
#define CP_COMMIT() asm volatile("cp.async.commit_group;" ::: "memory")
#define CP_WAIT(n)  asm volatile("cp.async.wait_group %0;" :: "n"(n) : "memory")

__device__ __forceinline__ void ldmx4(uint32_t* r, uint32_t addr) {
    asm volatile("ldmatrix.sync.aligned.m8n8.x4.shared.b16 {%0,%1,%2,%3}, [%4];"
                 : "=r"(r[0]), "=r"(r[1]), "=r"(r[2]), "=r"(r[3]) : "r"(addr));
}

__device__ __forceinline__ void mma_tf32(float* d, const uint32_t* a,
                                         const uint32_t* b) {
    asm volatile(
        "mma.sync.aligned.m16n8k8.row.col.f32.tf32.tf32.f32 "
        "{%0,%1,%2,%3}, {%4,%5,%6,%7}, {%8,%9}, {%0,%1,%2,%3};"
        : "+f"(d[0]), "+f"(d[1]), "+f"(d[2]), "+f"(d[3])
        : "r"(a[0]), "r"(a[1]), "r"(a[2]), "r"(a[3]), "r"(b[0]), "r"(b[1]));
}

// ---------------------------------------------------------------------------
__global__ void mqjs_init_kernel() { g_acc = 0.0; }

// Prep: per-row norms (fp32, exact) + tf32 conversions of x1 and p=(x1+x2)/2.
// One warp per row.
__global__ void mqjs_prep_kernel(const float* __restrict__ x1,
                                 const float* __restrict__ x2) {
    int warp = threadIdx.x >> 5;
    int lane = threadIdx.x & 31;
    int row  = blockIdx.x * 8 + warp;

    const float4* p1 = reinterpret_cast<const float4*>(x1 + (size_t)row * DDIM);
    const float4* p2 = reinterpret_cast<const float4*>(x2 + (size_t)row * DDIM);
    uint4* o1 = reinterpret_cast<uint4*>(g_x1t + (size_t)row * DDIM);
    uint4* op = reinterpret_cast<uint4*>(g_pt  + (size_t)row * DDIM);

    float s1 = 0.f, s2 = 0.f, sp = 0.f;
#pragma unroll
    for (int it = 0; it < 2; it++) {
        int pos = lane + it * 32;
        float4 a = p1[pos];
        float4 b = p2[pos];
        s1 += a.x * a.x + a.y * a.y + a.z * a.z + a.w * a.w;
        s2 += b.x * b.x + b.y * b.y + b.z * b.z + b.w * b.w;
        float px = 0.5f * (a.x + b.x), py = 0.5f * (a.y + b.y);
        float pz = 0.5f * (a.z + b.z), pw = 0.5f * (a.w + b.w);
        sp += px * px + py * py + pz * pz + pw * pw;
        uint4 ta = make_uint4(f2tf32(a.x), f2tf32(a.y), f2tf32(a.z), f2tf32(a.w));
        uint4 tp = make_uint4(f2tf32(px), f2tf32(py), f2tf32(pz), f2tf32(pw));
        o1[pos] = ta;
        op[pos] = tp;
    }
#pragma unroll
    for (int off = 16; off > 0; off >>= 1) {
        s1 += __shfl_xor_sync(0xFFFFFFFFu, s1, off);
        s2 += __shfl_xor_sync(0xFFFFFFFFu, s2, off);
        sp += __shfl_xor_sync(0xFFFFFFFFu, sp, off);
    }
    if (lane == 0) { g_n1sq[row] = s1; g_n2sq[row] = s2; g_npsq[row] = sp; }
}

// ---------------------------------------------------------------------------
// Triangular-tile fused quad-Gram (tf32 mma.sync):
//   S = X1_i.P_j^T, T = P_i.X1_j^T, G = P_i.P_j^T, D3 = X1_i.X1_j^T
// For tile pair (bi<=bj) these cover both (i,j) and (j,i) orientations:
//   d1_ij = n1[gm]+np[gn]-2S,   d2_ij = n2[gm]+np[gn]-2(2G-S)
//   d1_ji = n1[gn]+np[gm]-2T,   d2_ji = n2[gn]+np[gm]-2(2G-T)
//   d3    = n1[gm]+n1[gn]-2D3   (weight 2 off-diag, 1 on diag)
// CTA tile 64x64; 8 warps as 2(m)x4(n); warp tile 32(m)x16(n).
// Producers: cp.async from pre-converted tf32 globals; double-buffered.
// ---------------------------------------------------------------------------
__global__ __launch_bounds__(256, 2)
void mqjs_mma_kernel() {
    extern __shared__ char dsm[];
    __shared__ float s_nrm[6][TS];   // n1/n2/np @ib, n1/n2/np @jb
    __shared__ float s_red[8];

    const int tid  = threadIdx.x;
    const int lane = tid & 31;
    const int wid  = tid >> 5;
    const int wm   = wid & 1;
    const int wn   = wid >> 1;
    const int mb_w = wm * 32;
    const int nb_w = wn * 16;

    // ---- triangle decode: blockIdx.x -> (bi, bj), bi <= bj ----
    int t = blockIdx.x;
    int bi = (int)((2.f * NT + 1.f
                    - sqrtf((2.f * NT + 1.f) * (2.f * NT + 1.f) - 8.f * t)) * 0.5f);
    while ((bi + 1) * NT - ((bi + 1) * bi) / 2 <= t) bi++;
    while (bi * NT - (bi * (bi - 1)) / 2 > t) bi--;
    const int bj = bi + (t - (bi * NT - (bi * (bi - 1)) / 2));
    const int ib = bi * TS;
    const int jb = bj * TS;

    const uint32_t su = (smem_u32(dsm) + 1023u) & ~1023u;

    if (tid < TS) {
        s_nrm[0][tid] = g_n1sq[ib + tid];
        s_nrm[1][tid] = g_n2sq[ib + tid];
        s_nrm[2][tid] = g_npsq[ib + tid];
        s_nrm[3][tid] = g_n1sq[jb + tid];
        s_nrm[4][tid] = g_n2sq[jb + tid];
        s_nrm[5][tid] = g_npsq[jb + tid];
    }

    const uint4* x1i = reinterpret_cast<const uint4*>(g_x1t) + (size_t)ib * (DDIM / 4);
    const uint4* pi  = reinterpret_cast<const uint4*>(g_pt)  + (size_t)ib * (DDIM / 4);
    const uint4* x1j = reinterpret_cast<const uint4*>(g_x1t) + (size_t)jb * (DDIM / 4);
    const uint4* pj  = reinterpret_cast<const uint4*>(g_pt)  + (size_t)jb * (DDIM / 4);

    // per-thread cp.async geometry (2 reps x 4 tiles = 8 per chunk)
    const int r0 = tid >> 3,        c0 = tid & 7;
    const int r1 = (tid + 256) >> 3, c1 = (tid + 256) & 7;
    const uint32_t d0 = (uint32_t)(r0 * 128 + ((c0 ^ (r0 & 7)) << 4));
    const uint32_t d1 = (uint32_t)(r1 * 128 + ((c1 ^ (r1 & 7)) << 4));

#define ISSUE_CHUNK(cc, sb_)                                                   \
    {                                                                          \
        int g0 = r0 * (DDIM / 4) + (cc) * 8 + c0;                              \
        int g1 = r1 * (DDIM / 4) + (cc) * 8 + c1;                              \
        cp_async16((sb_) + OFF_X1I + d0, x1i + g0);                            \
        cp_async16((sb_) + OFF_PI  + d0, pi  + g0);                            \
        cp_async16((sb_) + OFF_X1J + d0, x1j + g0);                            \
        cp_async16((sb_) + OFF_PJ  + d0, pj  + g0);                            \
        cp_async16((sb_) + OFF_X1I + d1, x1i + g1);                            \
        cp_async16((sb_) + OFF_PI  + d1, pi  + g1);                            \
        cp_async16((sb_) + OFF_X1J + d1, x1j + g1);                            \
        cp_async16((sb_) + OFF_PJ  + d1, pj  + g1);                            \
        CP_COMMIT();                                                           \
    }

    // ldmatrix per-lane constants
    const int arow = (lane & 7) | (((lane >> 3) & 1) << 3);
    const uint32_t ahi  = (uint32_t)(((lane >> 4) & 1) << 4);
    const uint32_t aswz = (uint32_t)((arow & 7) << 4);
    const uint32_t aRow0 = (uint32_t)((mb_w + arow) * 128);
    const int brow = (lane & 7) | (((lane >> 4) & 1) << 3);
    const uint32_t bhi  = (uint32_t)(((lane >> 3) & 1) << 4);
    const uint32_t bswz = (uint32_t)((brow & 7) << 4);
    const uint32_t bRow0 = (uint32_t)((nb_w + brow) * 128);

    float aS[2][2][4], aT[2][2][4], aG[2][2][4], aD[2][2][4];
#pragma unroll
    for (int mt = 0; mt < 2; mt++)
#pragma unroll
        for (int n8 = 0; n8 < 2; n8++)
#pragma unroll
            for (int e = 0; e < 4; e++) {
                aS[mt][n8][e] = 0.f; aT[mt][n8][e] = 0.f;
                aG[mt][n8][e] = 0.f; aD[mt][n8][e] = 0.f;
            }

    ISSUE_CHUNK(0, su);

    for (int c = 0; c < NCHUNK; c++) {
        const int b = c & 1;
        const uint32_t sb = su + (uint32_t)b * STAGE_BYTES;
        if (c < NCHUNK - 1)
            ISSUE_CHUNK(c + 1, su + (uint32_t)(1 - b) * STAGE_BYTES);
        if (c < NCHUNK - 1) { CP_WAIT(1); } else { CP_WAIT(0); }
        __syncthreads();

#pragma unroll
        for (int ks = 0; ks < 4; ks++) {
            const uint32_t ak = ((uint32_t)(ks * 32) + ahi) ^ aswz;
            const uint32_t bk = ((uint32_t)(ks * 32) + bhi) ^ bswz;
            uint32_t fa1[8], fap[8], fb1[4], fbp[4];
            ldmx4(fa1 + 0, sb + OFF_X1I + aRow0 + ak);
            ldmx4(fa1 + 4, sb + OFF_X1I + aRow0 + 2048 + ak);
            ldmx4(fap + 0, sb + OFF_PI  + aRow0 + ak);
            ldmx4(fap + 4, sb + OFF_PI  + aRow0 + 2048 + ak);
            ldmx4(fb1,     sb + OFF_X1J + bRow0 + bk);
            ldmx4(fbp,     sb + OFF_PJ  + bRow0 + bk);
#pragma unroll
            for (int mt = 0; mt < 2; mt++) {
#pragma unroll
                for (int n8 = 0; n8 < 2; n8++) {
                    mma_tf32(aS[mt][n8], fa1 + mt * 4, fbp + n8 * 2);
                    mma_tf32(aT[mt][n8], fap + mt * 4, fb1 + n8 * 2);
                    mma_tf32(aG[mt][n8], fap + mt * 4, fbp + n8 * 2);
                    mma_tf32(aD[mt][n8], fa1 + mt * 4, fb1 + n8 * 2);
                }
            }
        }
        __syncthreads();
    }

    // ---- epilogue ----
    const float cse = (float)NROWS / (float)(NROWS - 1);
    const float wT  = (bi != bj) ? 1.f : 0.f;
    const float w3c = ((bi != bj) ? 2.f : 1.f) * cse * 0.5f;
    const int rbase = mb_w + (lane >> 2);
    const int cbase = nb_w + (lane & 3) * 2;

    float part = 0.f;
#pragma unroll
    for (int mt = 0; mt < 2; mt++) {
        const int rA = rbase + mt * 16;
        const int rB = rA + 8;
        const float n1iA = s_nrm[0][rA], n2iA = s_nrm[1][rA], npiA = s_nrm[2][rA];
        const float n1iB = s_nrm[0][rB], n2iB = s_nrm[1][rB], npiB = s_nrm[2][rB];
#pragma unroll
        for (int n8 = 0; n8 < 2; n8++) {
            const int cA = cbase + n8 * 8;
            const int cB = cA + 1;
            const float n1jA = s_nrm[3][cA], n2jA = s_nrm[4][cA], npjA = s_nrm[5][cA];
            const float n1jB = s_nrm[3][cB], n2jB = s_nrm[4][cB], npjB = s_nrm[5][cB];
            const float* S = aS[mt][n8];
            const float* T = aT[mt][n8];
            const float* G = aG[mt][n8];
            const float* D = aD[mt][n8];
#pragma unroll
            for (int e = 0; e < 4; e++) {
                const float n1i = (e < 2) ? n1iA : n1iB;
                const float n2i = (e < 2) ? n2iA : n2iB;
                const float npi = (e < 2) ? npiA : npiB;
                const float n1j = (e & 1) ? n1jB : n1jA;
                const float n2j = (e & 1) ? n2jB : n2jA;
                const float npj = (e & 1) ? npjB : npjA;
                const float s = S[e], tt = T[e], g2 = 2.f * G[e], dd = D[e];
                float d1a = n1i + npj - 2.f * s;
                float d2a = n2i + npj - 2.f * (g2 - s);
                float d1b = n1j + npi - 2.f * tt;
                float d2b = n2j + npi - 2.f * (g2 - tt);
                float d3  = n1i + n1j - 2.f * dd;
                part += 0.5f * (__logf(fmaxf(d1a, 1.f)) + __logf(fmaxf(d2a, 1.f)));
                part += wT * 0.5f * (__logf(fmaxf(d1b, 1.f)) + __logf(fmaxf(d2b, 1.f)));
                part -= w3c * __logf(fmaxf(d3, 1.f));
            }
        }
    }

    // ---- reduction ----
#pragma unroll
    for (int off = 16; off > 0; off >>= 1)
        part += __shfl_xor_sync(0xFFFFFFFFu, part, off);
    if (lane == 0) s_red[wid] = part;
    __syncthreads();
    if (tid == 0) {
        float tot = 0.f;
#pragma unroll
        for (int w = 0; w < 8; w++) tot += s_red[w];
        atomicAdd(&g_acc, (double)tot);
    }
}

// ---------------------------------------------------------------------------
__global__ void mqjs_finalize_kernel(float* out) {
    out[0] = (float)(g_acc / (double)NROWS);
}

// ---------------------------------------------------------------------------
extern "C" void kernel_launch(void* const* d_in, const int* in_sizes, int n_in,
                              void* d_out, int out_size) {
    const float* x1 = (const float*)d_in[0];   // input
    const float* x2 = (const float*)d_in[1];   // target
    float* out = (float*)d_out;

    cudaFuncSetAttribute(mqjs_mma_kernel,
                         cudaFuncAttributeMaxDynamicSharedMemorySize, DSMEM_BYTES);

    mqjs_init_kernel<<<1, 1>>>();
    mqjs_prep_kernel<<<NROWS / 8, 256>>>(x1, x2);
    mqjs_mma_kernel<<<NTILES, 256, DSMEM_BYTES>>>();
    mqjs_finalize_kernel<<<1, 1>>>(out);
}

// round 12
// speedup vs baseline: 11.9916x; 1.7569x over previous
#include <cuda_runtime.h>
#include <cuda_fp16.h>
#include <cstdint>

#define NROWS 8192
#define DDIM  256
#define NT    128                     // 64-row tiles per dimension
#define TS    64                      // tile size
#define NTILES (NT * (NT + 1) / 2)    // 8256 upper-triangle tile pairs
#define KCH   64                      // halfs per k-chunk (128 B rows)
#define NCHUNK (DDIM / KCH)           // 4
#define HROW4 (DDIM / 8)              // uint4 per row of fp16 data (32)
#define OFF_X1I 0
#define OFF_PI  8192
#define OFF_X1J 16384
#define OFF_PJ  24576
#define STAGE_BYTES 32768
#define DSMEM_BYTES (2 * STAGE_BYTES + 1024)

// Scratch (no allocations allowed)
__device__ float    g_n1sq[NROWS];
__device__ float    g_n2sq[NROWS];
__device__ float    g_npsq[NROWS];
__device__ uint32_t g_x1h[NROWS * DDIM / 2];   // fp16 x1 (packed half2)
__device__ uint32_t g_ph [NROWS * DDIM / 2];   // fp16 p  (packed half2)
__device__ double   g_acc;

// ---------------------------------------------------------------------------
// Helpers (generic sm_80+ PTX only — ptxas here targets plain sm_103)
// ---------------------------------------------------------------------------
__device__ __forceinline__ uint32_t smem_u32(const void* p) {
    uint32_t a;
    asm("{ .reg .u64 t; cvta.to.shared.u64 t, %1; cvt.u32.u64 %0, t; }"
        : "=r"(a) : "l"(p));
    return a;
}

__device__ __forceinline__ void cp_async16(uint32_t smem_addr, const void* gptr) {
    asm volatile("cp.async.cg.shared.global [%0], [%1], 16;"
                 :: "r"(smem_addr), "l"(gptr) : "memory");
}
#define CP_COMMIT() asm volatile("cp.async.commit_group;" ::: "memory")
#define CP_WAIT(n)  asm volatile("cp.async.wait_group %0;" :: "n"(n) : "memory")

__device__ __forceinline__ void ldmx4(uint32_t* r, uint32_t addr) {
    asm volatile("ldmatrix.sync.aligned.m8n8.x4.shared.b16 {%0,%1,%2,%3}, [%4];"
                 : "=r"(r[0]), "=r"(r[1]), "=r"(r[2]), "=r"(r[3]) : "r"(addr));
}

// fp16 MMA, fp32 accumulate: m16n8k16.row.col
__device__ __forceinline__ void mma_f16(float* d, const uint32_t* a,
                                        const uint32_t* b) {
    asm volatile(
        "mma.sync.aligned.m16n8k16.row.col.f32.f16.f16.f32 "
        "{%0,%1,%2,%3}, {%4,%5,%6,%7}, {%8,%9}, {%0,%1,%2,%3};"
        : "+f"(d[0]), "+f"(d[1]), "+f"(d[2]), "+f"(d[3])
        : "r"(a[0]), "r"(a[1]), "r"(a[2]), "r"(a[3]), "r"(b[0]), "r"(b[1]));
}

// ---------------------------------------------------------------------------
__global__ void mqjs_init_kernel() { g_acc = 0.0; }

// Prep: per-row norms (fp32, exact) + fp16 conversions of x1 and p=(x1+x2)/2.
// One warp per row.
__global__ void mqjs_prep_kernel(const float* __restrict__ x1,
                                 const float* __restrict__ x2) {
    int warp = threadIdx.x >> 5;
    int lane = threadIdx.x & 31;
    int row  = blockIdx.x * 8 + warp;

    const float4* p1 = reinterpret_cast<const float4*>(x1 + (size_t)row * DDIM);
    const float4* p2 = reinterpret_cast<const float4*>(x2 + (size_t)row * DDIM);
    uint2* o1 = reinterpret_cast<uint2*>(g_x1h + (size_t)row * (DDIM / 2));
    uint2* op = reinterpret_cast<uint2*>(g_ph  + (size_t)row * (DDIM / 2));

    float s1 = 0.f, s2 = 0.f, sp = 0.f;
#pragma unroll
    for (int it = 0; it < 2; it++) {
        int pos = lane + it * 32;
        float4 a = p1[pos];
        float4 b = p2[pos];
        s1 += a.x * a.x + a.y * a.y + a.z * a.z + a.w * a.w;
        s2 += b.x * b.x + b.y * b.y + b.z * b.z + b.w * b.w;
        float px = 0.5f * (a.x + b.x), py = 0.5f * (a.y + b.y);
        float pz = 0.5f * (a.z + b.z), pw = 0.5f * (a.w + b.w);
        sp += px * px + py * py + pz * pz + pw * pw;
        __half2 axy = __floats2half2_rn(a.x, a.y);
        __half2 azw = __floats2half2_rn(a.z, a.w);
        __half2 pxy = __floats2half2_rn(px, py);
        __half2 pzw = __floats2half2_rn(pz, pw);
        uint2 ua, up;
        ua.x = *reinterpret_cast<uint32_t*>(&axy);
        ua.y = *reinterpret_cast<uint32_t*>(&azw);
        up.x = *reinterpret_cast<uint32_t*>(&pxy);
        up.y = *reinterpret_cast<uint32_t*>(&pzw);
        o1[pos] = ua;
        op[pos] = up;
    }
#pragma unroll
    for (int off = 16; off > 0; off >>= 1) {
        s1 += __shfl_xor_sync(0xFFFFFFFFu, s1, off);
        s2 += __shfl_xor_sync(0xFFFFFFFFu, s2, off);
        sp += __shfl_xor_sync(0xFFFFFFFFu, sp, off);
    }
    if (lane == 0) { g_n1sq[row] = s1; g_n2sq[row] = s2; g_npsq[row] = sp; }
}

// ---------------------------------------------------------------------------
// Triangular-tile fused quad-Gram (fp16 mma.sync, fp32 accum):
//   S = X1_i.P_j^T, T = P_i.X1_j^T, G = P_i.P_j^T, D3 = X1_i.X1_j^T
// For tile pair (bi<=bj) these cover both (i,j) and (j,i) orientations:
//   d1_ij = n1[gm]+np[gn]-2S,   d2_ij = n2[gm]+np[gn]-2(2G-S)
//   d1_ji = n1[gn]+np[gm]-2T,   d2_ji = n2[gn]+np[gm]-2(2G-T)
//   d3    = n1[gm]+n1[gn]-2D3   (weight 2 off-diag, 1 on diag)
// CTA tile 64x64; 8 warps as 2(m)x4(n); warp tile 32(m)x16(n).
// Producers: cp.async from pre-converted fp16 globals; double-buffered.
// Rows are 128 B (64 halfs) -> same XOR swizzle/ldmatrix geometry as tf32 ver.
// ---------------------------------------------------------------------------
__global__ __launch_bounds__(256, 2)
void mqjs_mma_kernel() {
    extern __shared__ char dsm[];
    __shared__ float s_nrm[6][TS];   // n1/n2/np @ib, n1/n2/np @jb
    __shared__ float s_red[8];

    const int tid  = threadIdx.x;
    const int lane = tid & 31;
    const int wid  = tid >> 5;
    const int wm   = wid & 1;
    const int wn   = wid >> 1;
    const int mb_w = wm * 32;
    const int nb_w = wn * 16;

    // ---- triangle decode: blockIdx.x -> (bi, bj), bi <= bj ----
    int t = blockIdx.x;
    int bi = (int)((2.f * NT + 1.f
                    - sqrtf((2.f * NT + 1.f) * (2.f * NT + 1.f) - 8.f * t)) * 0.5f);
    while ((bi + 1) * NT - ((bi + 1) * bi) / 2 <= t) bi++;
    while (bi * NT - (bi * (bi - 1)) / 2 > t) bi--;
    const int bj = bi + (t - (bi * NT - (bi * (bi - 1)) / 2));
    const int ib = bi * TS;
    const int jb = bj * TS;

    const uint32_t su = (smem_u32(dsm) + 1023u) & ~1023u;

    if (tid < TS) {
        s_nrm[0][tid] = g_n1sq[ib + tid];
        s_nrm[1][tid] = g_n2sq[ib + tid];
        s_nrm[2][tid] = g_npsq[ib + tid];
        s_nrm[3][tid] = g_n1sq[jb + tid];
        s_nrm[4][tid] = g_n2sq[jb + tid];
        s_nrm[5][tid] = g_npsq[jb + tid];
    }

    const uint4* x1i = reinterpret_cast<const uint4*>(g_x1h) + (size_t)ib * HROW4;
    const uint4* pi  = reinterpret_cast<const uint4*>(g_ph)  + (size_t)ib * HROW4;
    const uint4* x1j = reinterpret_cast<const uint4*>(g_x1h) + (size_t)jb * HROW4;
    const uint4* pj  = reinterpret_cast<const uint4*>(g_ph)  + (size_t)jb * HROW4;

    // per-thread cp.async geometry (2 reps x 4 tiles = 8 per chunk)
    const int r0 = tid >> 3,         c0 = tid & 7;
    const int r1 = (tid + 256) >> 3, c1 = (tid + 256) & 7;
    const uint32_t d0 = (uint32_t)(r0 * 128 + ((c0 ^ (r0 & 7)) << 4));
    const uint32_t d1 = (uint32_t)(r1 * 128 + ((c1 ^ (r1 & 7)) << 4));

#define ISSUE_CHUNK(cc, sb_)                                                   \
    {                                                                          \
        int g0 = r0 * HROW4 + (cc) * 8 + c0;                                   \
        int g1 = r1 * HROW4 + (cc) * 8 + c1;                                   \
        cp_async16((sb_) + OFF_X1I + d0, x1i + g0);                            \
        cp_async16((sb_) + OFF_PI  + d0, pi  + g0);                            \
        cp_async16((sb_) + OFF_X1J + d0, x1j + g0);                            \
        cp_async16((sb_) + OFF_PJ  + d0, pj  + g0);                            \
        cp_async16((sb_) + OFF_X1I + d1, x1i + g1);                            \
        cp_async16((sb_) + OFF_PI  + d1, pi  + g1);                            \
        cp_async16((sb_) + OFF_X1J + d1, x1j + g1);                            \
        cp_async16((sb_) + OFF_PJ  + d1, pj  + g1);                            \
        CP_COMMIT();                                                           \
    }

    // ldmatrix per-lane constants (32-byte k-step, same geometry as tf32 ver)
    const int arow = (lane & 7) | (((lane >> 3) & 1) << 3);
    const uint32_t ahi  = (uint32_t)(((lane >> 4) & 1) << 4);
    const uint32_t aswz = (uint32_t)((arow & 7) << 4);
    const uint32_t aRow0 = (uint32_t)((mb_w + arow) * 128);
    const int brow = (lane & 7) | (((lane >> 4) & 1) << 3);
    const uint32_t bhi  = (uint32_t)(((lane >> 3) & 1) << 4);
    const uint32_t bswz = (uint32_t)((brow & 7) << 4);
    const uint32_t bRow0 = (uint32_t)((nb_w + brow) * 128);

    float aS[2][2][4], aT[2][2][4], aG[2][2][4], aD[2][2][4];
#pragma unroll
    for (int mt = 0; mt < 2; mt++)
#pragma unroll
        for (int n8 = 0; n8 < 2; n8++)
#pragma unroll
            for (int e = 0; e < 4; e++) {
                aS[mt][n8][e] = 0.f; aT[mt][n8][e] = 0.f;
                aG[mt][n8][e] = 0.f; aD[mt][n8][e] = 0.f;
            }

    ISSUE_CHUNK(0, su);

    for (int c = 0; c < NCHUNK; c++) {
        const int b = c & 1;
        const uint32_t sb = su + (uint32_t)b * STAGE_BYTES;
        if (c < NCHUNK - 1)
            ISSUE_CHUNK(c + 1, su + (uint32_t)(1 - b) * STAGE_BYTES);
        if (c < NCHUNK - 1) { CP_WAIT(1); } else { CP_WAIT(0); }
        __syncthreads();

#pragma unroll
        for (int ks = 0; ks < 4; ks++) {     // K=16 halfs per step, 4 steps/chunk
            const uint32_t ak = ((uint32_t)(ks * 32) + ahi) ^ aswz;
            const uint32_t bk = ((uint32_t)(ks * 32) + bhi) ^ bswz;
            uint32_t fa1[8], fap[8], fb1[4], fbp[4];
            ldmx4(fa1 + 0, sb + OFF_X1I + aRow0 + ak);
            ldmx4(fa1 + 4, sb + OFF_X1I + aRow0 + 2048 + ak);
            ldmx4(fap + 0, sb + OFF_PI  + aRow0 + ak);
            ldmx4(fap + 4, sb + OFF_PI  + aRow0 + 2048 + ak);
            ldmx4(fb1,     sb + OFF_X1J + bRow0 + bk);
            ldmx4(fbp,     sb + OFF_PJ  + bRow0 + bk);
#pragma unroll
            for (int mt = 0; mt < 2; mt++) {
#pragma unroll
                for (int n8 = 0; n8 < 2; n8++) {
                    mma_f16(aS[mt][n8], fa1 + mt * 4, fbp + n8 * 2);
                    mma_f16(aT[mt][n8], fap + mt * 4, fb1 + n8 * 2);
                    mma_f16(aG[mt][n8], fap + mt * 4, fbp + n8 * 2);
                    mma_f16(aD[mt][n8], fa1 + mt * 4, fb1 + n8 * 2);
                }
            }
        }
        __syncthreads();
    }

    // ---- epilogue ----
    const float cse = (float)NROWS / (float)(NROWS - 1);
    const float wT  = (bi != bj) ? 1.f : 0.f;
    const float w3c = ((bi != bj) ? 2.f : 1.f) * cse * 0.5f;
    const int rbase = mb_w + (lane >> 2);
    const int cbase = nb_w + (lane & 3) * 2;

    float part = 0.f;
#pragma unroll
    for (int mt = 0; mt < 2; mt++) {
        const int rA = rbase + mt * 16;
        const int rB = rA + 8;
        const float n1iA = s_nrm[0][rA], n2iA = s_nrm[1][rA], npiA = s_nrm[2][rA];
        const float n1iB = s_nrm[0][rB], n2iB = s_nrm[1][rB], npiB = s_nrm[2][rB];
#pragma unroll
        for (int n8 = 0; n8 < 2; n8++) {
            const int cA = cbase + n8 * 8;
            const int cB = cA + 1;
            const float n1jA = s_nrm[3][cA], n2jA = s_nrm[4][cA], npjA = s_nrm[5][cA];
            const float n1jB = s_nrm[3][cB], n2jB = s_nrm[4][cB], npjB = s_nrm[5][cB];
            const float* S = aS[mt][n8];
            const float* T = aT[mt][n8];
            const float* G = aG[mt][n8];
            const float* D = aD[mt][n8];
#pragma unroll
            for (int e = 0; e < 4; e++) {
                const float n1i = (e < 2) ? n1iA : n1iB;
                const float n2i = (e < 2) ? n2iA : n2iB;
                const float npi = (e < 2) ? npiA : npiB;
                const float n1j = (e & 1) ? n1jB : n1jA;
                const float n2j = (e & 1) ? n2jB : n2jA;
                const float npj = (e & 1) ? npjB : npjA;
                const float s = S[e], tt = T[e], g2 = 2.f * G[e], dd = D[e];
                float d1a = n1i + npj - 2.f * s;
                float d2a = n2i + npj - 2.f * (g2 - s);
                float d1b = n1j + npi - 2.f * tt;
                float d2b = n2j + npi - 2.f * (g2 - tt);
                float d3  = n1i + n1j - 2.f * dd;
                part += 0.5f * (__logf(fmaxf(d1a, 1.f)) + __logf(fmaxf(d2a, 1.f)));
                part += wT * 0.5f * (__logf(fmaxf(d1b, 1.f)) + __logf(fmaxf(d2b, 1.f)));
                part -= w3c * __logf(fmaxf(d3, 1.f));
            }
        }
    }

    // ---- reduction ----
#pragma unroll
    for (int off = 16; off > 0; off >>= 1)
        part += __shfl_xor_sync(0xFFFFFFFFu, part, off);
    if (lane == 0) s_red[wid] = part;
    __syncthreads();
    if (tid == 0) {
        float tot = 0.f;
#pragma unroll
        for (int w = 0; w < 8; w++) tot += s_red[w];
        atomicAdd(&g_acc, (double)tot);
    }
}

// ---------------------------------------------------------------------------
__global__ void mqjs_finalize_kernel(float* out) {
    out[0] = (float)(g_acc / (double)NROWS);
}

// ---------------------------------------------------------------------------
extern "C" void kernel_launch(void* const* d_in, const int* in_sizes, int n_in,
                              void* d_out, int out_size) {
    const float* x1 = (const float*)d_in[0];   // input
    const float* x2 = (const float*)d_in[1];   // target
    float* out = (float*)d_out;

    cudaFuncSetAttribute(mqjs_mma_kernel,
                         cudaFuncAttributeMaxDynamicSharedMemorySize, DSMEM_BYTES);

    mqjs_init_kernel<<<1, 1>>>();
    mqjs_prep_kernel<<<NROWS / 8, 256>>>(x1, x2);
    mqjs_mma_kernel<<<NTILES, 256, DSMEM_BYTES>>>();
    mqjs_finalize_kernel<<<1, 1>>>(out);
}